// round 9
// baseline (speedup 1.0000x reference)
#include <cuda_runtime.h>
#include <cstdint>

// Problem constants (fixed by the dataset: B=1, P=8192, N=16384, C=64)
#define GRID_DIM 10
#define NCELLS   (GRID_DIM * GRID_DIM * GRID_DIM)
#define NPTS_MAX 16384
#define CFEAT    64
#define OUTC     115          // 64 fcd + 3 xyz + 24 sin + 24 cos
#define KNN      10
#define R2F      0.01f
#define RADIUSF  0.1f
#define CANDMAX  128          // per-query candidate cap (E ~ 68.6, sigma ~ 8.3)
#define WPB      4            // warps (queries) per block
#define BTHR     256          // build threads per block
#define UINF     0xFFFFFFFFu

// ---- scratch: static __device__ arrays (no allocation allowed) ----
__device__ int    g_cell_count[NCELLS];      // zero-init; self-reset each launch
__device__ int    g_cell_start[NCELLS + 1];
__device__ int    g_cell_cursor[NCELLS];
__device__ int    g_ticket;                  // MONOTONIC across replays (no reset)
__device__ float4 g_sorted[NPTS_MAX + 96];   // {x,y,z,|p|^2}; +96 zero pad (safe OOS loads)
__device__ int    g_sidx[NPTS_MAX];          // original index

__device__ __forceinline__ int cell_coord(float v) {
    int c = (int)(v * 10.0f);
    return c < 0 ? 0 : (c > 9 ? 9 : c);
}
__device__ __forceinline__ int cell_of(float x, float y, float z) {
    return (cell_coord(z) * GRID_DIM + cell_coord(y)) * GRID_DIM + cell_coord(x);
}

// ---- fused build: count -> (last block) scan -> release -> scatter ----
// grid must be fully resident (64 blocks << 148 SMs). Ticket is monotonic:
// each launch contributes gridDim.x+1 increments, so no reset is required.
__global__ void __launch_bounds__(BTHR)
build_kernel(const float* __restrict__ pcd, int N) {
    const int t = threadIdx.x;
    const int i = blockIdx.x * BTHR + t;
    const int nb = gridDim.x;

    float x = 0.f, y = 0.f, z = 0.f, pp = 0.f;
    int c = 0;
    const bool valid = (i < N);
    if (valid) {
        x = pcd[3 * i]; y = pcd[3 * i + 1]; z = pcd[3 * i + 2];
        pp = __fadd_rn(__fadd_rn(__fmul_rn(x, x), __fmul_rn(y, y)),
                       __fmul_rn(z, z));            // |p|^2 as reference
        c = cell_of(x, y, z);
        atomicAdd(&g_cell_count[c], 1);
    }
    __syncthreads();

    __shared__ int s_release, s_last;
    if (t == 0) {
        __threadfence();
        int tk = atomicAdd(&g_ticket, 1);
        int base = tk - (tk % (nb + 1));
        s_release = base + nb + 1;
        s_last = ((tk % (nb + 1)) == nb - 1);
    }
    __syncthreads();

    if (s_last) {
        // 256 threads scan 1000 cells: 4 serial each + shfl warp-scan hierarchy
        __shared__ int warp_sums[8];
        const int lane = t & 31, wid = t >> 5;
        const int c0 = t * 4;
        int loc[4], pref = 0;
        #pragma unroll
        for (int r = 0; r < 4; r++) {
            int cc = c0 + r;
            int v = (cc < NCELLS) ? g_cell_count[cc] : 0;
            loc[r] = pref;                 // exclusive within thread
            pref += v;
            if (cc < NCELLS) g_cell_count[cc] = 0;   // reset for next launch
        }
        int inc = pref;
        #pragma unroll
        for (int off = 1; off < 32; off <<= 1) {
            int o = __shfl_up_sync(0xffffffffu, inc, off);
            if (lane >= off) inc += o;
        }
        if (lane == 31) warp_sums[wid] = inc;
        __syncthreads();
        if (wid == 0) {
            int v = (lane < 8) ? warp_sums[lane] : 0;
            int s = v;
            #pragma unroll
            for (int off = 1; off < 8; off <<= 1) {
                int o = __shfl_up_sync(0xffffffffu, s, off);
                if (lane >= off) s += o;
            }
            if (lane < 8) warp_sums[lane] = s - v;   // exclusive warp offsets
        }
        __syncthreads();
        const int base = warp_sums[wid] + (inc - pref);
        #pragma unroll
        for (int r = 0; r < 4; r++) {
            int cc = c0 + r;
            if (cc < NCELLS) {
                int e = base + loc[r];
                g_cell_start[cc] = e;
                g_cell_cursor[cc] = e;
            }
        }
        if (t == BTHR - 1) g_cell_start[NCELLS] = base + pref;
        __syncthreads();
        if (t == 0) {
            __threadfence();
            atomicAdd(&g_ticket, 1);       // release
        }
    }

    // wait for release
    if (t == 0) {
        const int rel = s_release;
        while (*((volatile int*)&g_ticket) < rel) __nanosleep(32);
    }
    __syncthreads();
    __threadfence();

    // scatter with values still in registers
    if (valid) {
        int pos = atomicAdd(&g_cell_cursor[c], 1);
        g_sorted[pos] = make_float4(x, y, z, pp);
        g_sidx[pos] = i;
    }
}

// ---- main: warp-per-query radius KNN + aggregate + positional encoding ----
__global__ void __launch_bounds__(WPB * 32)
knn_kernel(const float* __restrict__ xyz,
           const float* __restrict__ feat,
           float* __restrict__ out, int P) {
    __shared__ uint2 buf[WPB][CANDMAX];    // {ordered_d2_bits, sorted_pos}

    const int w    = threadIdx.x >> 5;
    const int lane = threadIdx.x & 31;
    const int q    = blockIdx.x * WPB + w;
    if (q >= P) return;                    // warp-uniform

    const float qx = xyz[3 * q], qy = xyz[3 * q + 1], qz = xyz[3 * q + 2];
    const float qq = __fadd_rn(__fadd_rn(__fmul_rn(qx, qx), __fmul_rn(qy, qy)),
                               __fmul_rn(qz, qz));

    const int iy = cell_coord(qy), iz = cell_coord(qz);
    const int y0 = max(iy - 1, 0), y1 = min(iy + 1, GRID_DIM - 1);
    const int z0 = max(iz - 1, 0), z1 = min(iz + 1, GRID_DIM - 1);

    // collect row segments (warp-uniform, <= 9)
    int sgS[9], sgE[9];
    int nsg = 0;
    for (int zz = z0; zz <= z1; zz++) {
        float dz = fmaxf(0.0f, fmaxf(0.1f * zz - qz, qz - 0.1f * (zz + 1)));
        float dz2 = dz * dz;
        for (int yy = y0; yy <= y1; yy++) {
            float dy = fmaxf(0.0f, fmaxf(0.1f * yy - qy, qy - 0.1f * (yy + 1)));
            float rowd2 = fmaf(dy, dy, dz2);
            if (rowd2 > R2F + 1e-6f) continue;
            float rx = sqrtf(fmaxf(R2F + 1e-7f - rowd2, 0.0f)) + 1e-6f;
            int xa = cell_coord(qx - rx);
            int xb = cell_coord(qx + rx);
            const int cbase = (zz * GRID_DIM + yy) * GRID_DIM;
            int s = g_cell_start[cbase + xa];
            int e = g_cell_start[cbase + xb + 1];
            if (e > s) { sgS[nsg] = s; sgE[nsg] = e; nsg++; }
        }
    }

    // pipelined scan over the flattened chunk stream (64 pts / chunk):
    // next chunk's loads issue BEFORE current chunk is processed.
    int count = 0;
    int si = 0;
    int j0 = (nsg > 0) ? sgS[0] : 0;
    float4 pa = g_sorted[j0 + lane];
    float4 pb = g_sorted[j0 + 32 + lane];
    const unsigned lmask = (1u << lane) - 1u;
    while (si < nsg) {
        const int ce = sgE[si];
        // next chunk coordinates
        int nsi = si, nj0 = j0 + 64;
        if (nj0 >= ce) { nsi = si + 1; nj0 = (nsi < nsg) ? sgS[nsi] : 0; }
        // prefetch next chunk (always safe: padded array / index 0)
        float4 na = g_sorted[nj0 + lane];
        float4 nb = g_sorted[nj0 + 32 + lane];
        // process current chunk
        float dota = fmaf(qz, pa.z, fmaf(qy, pa.y, __fmul_rn(qx, pa.x)));
        float d2a  = __fsub_rn(__fadd_rn(qq, pa.w), __fmul_rn(2.0f, dota));
        float dotb = fmaf(qz, pb.z, fmaf(qy, pb.y, __fmul_rn(qx, pb.x)));
        float d2b  = __fsub_rn(__fadd_rn(qq, pb.w), __fmul_rn(2.0f, dotb));
        const int ja = j0 + lane;
        const int jb = ja + 32;
        bool pra = (ja < ce) && (d2a < R2F);
        bool prb = (jb < ce) && (d2b < R2F);
        unsigned ba = __ballot_sync(0xffffffffu, pra);
        unsigned bb = __ballot_sync(0xffffffffu, prb);
        if (pra) {
            int b = __float_as_int(d2a);
            unsigned u = (unsigned)b ^ ((b >= 0) ? 0x80000000u : 0xFFFFFFFFu);
            int pos = count + __popc(ba & lmask);
            if (pos < CANDMAX) buf[w][pos] = make_uint2(u, (unsigned)ja);
        }
        int ca = __popc(ba);
        if (prb) {
            int b = __float_as_int(d2b);
            unsigned u = (unsigned)b ^ ((b >= 0) ? 0x80000000u : 0xFFFFFFFFu);
            int pos = count + ca + __popc(bb & lmask);
            if (pos < CANDMAX) buf[w][pos] = make_uint2(u, (unsigned)jb);
        }
        count += ca + __popc(bb);          // uniform across the warp
        si = nsi; j0 = nj0; pa = na; pb = nb;
    }
    __syncwarp();

    const int m = min(count, CANDMAX);

    // per-lane slots in named registers (no dynamic indexing)
    unsigned vd0, vd1, vd2, vd3, vp0, vp1, vp2, vp3;
    {
        uint2 e0 = (lane      < m) ? buf[w][lane]      : make_uint2(UINF, 0u);
        uint2 e1 = (lane + 32 < m) ? buf[w][lane + 32] : make_uint2(UINF, 0u);
        uint2 e2 = (lane + 64 < m) ? buf[w][lane + 64] : make_uint2(UINF, 0u);
        uint2 e3 = (lane + 96 < m) ? buf[w][lane + 96] : make_uint2(UINF, 0u);
        vd0 = e0.x; vp0 = e0.y;  vd1 = e1.x; vp1 = e1.y;
        vd2 = e2.x; vp2 = e2.y;  vd3 = e3.x; vp3 = e3.y;
    }

    unsigned kd2 = UINF, kpos = 0u;
    #pragma unroll
    for (int i = 0; i < KNN; i++) {
        bool c01 = (vd0 < vd1) || (vd0 == vd1 && vp0 <= vp1);
        unsigned m01 = c01 ? vd0 : vd1, p01 = c01 ? vp0 : vp1;
        int s01 = c01 ? 0 : 1;
        bool c23 = (vd2 < vd3) || (vd2 == vd3 && vp2 <= vp3);
        unsigned m23 = c23 ? vd2 : vd3, p23 = c23 ? vp2 : vp3;
        int s23 = c23 ? 2 : 3;
        bool cf = (m01 < m23) || (m01 == m23 && p01 <= p23);
        unsigned lmin = cf ? m01 : m23, lpos = cf ? p01 : p23;
        int lslot = cf ? s01 : s23;

        unsigned gmin = __reduce_min_sync(0xffffffffu, lmin);
        unsigned cnd  = (lmin == gmin) ? lpos : UINF;
        unsigned wpos = __reduce_min_sync(0xffffffffu, cnd);
        if (lane == i) { kd2 = gmin; kpos = wpos; }

        bool winner = (lmin == gmin) & (lpos == wpos);
        vd0 = (winner && lslot == 0) ? UINF : vd0;
        vd1 = (winner && lslot == 1) ? UINF : vd1;
        vd2 = (winner && lslot == 2) ? UINF : vd2;
        vd3 = (winner && lslot == 3) ? UINF : vd3;
    }

    // weights (per reference numerics)
    float wr = 0.0f;
    int nidx = 0;
    if (kd2 != UINF) {
        unsigned ub = kd2 ^ (((int)kd2 < 0) ? 0x80000000u : 0xFFFFFFFFu);
        float d2 = __int_as_float((int)ub);
        float dist = sqrtf(fmaxf(d2, 0.0f) + 1e-12f);
        if (dist < RADIUSF) wr = 1.0f / (dist + 1e-8f);
        nidx = g_sidx[kpos];               // only winner lanes load this
    }
    float ws = wr;
    #pragma unroll
    for (int off = 16; off; off >>= 1) ws += __shfl_xor_sync(0xffffffffu, ws, off);
    float wn = wr / (ws + 1e-8f);

    // weighted feature gather: each lane owns channels (2*lane, 2*lane+1)
    const float* fbase = feat + 2 * lane;
    float acc0 = 0.0f, acc1 = 0.0f;
    #pragma unroll
    for (int i = 0; i < KNN; i++) {
        float wi = __shfl_sync(0xffffffffu, wn, i);
        int ii = __shfl_sync(0xffffffffu, nidx, i);
        const float2 f2 = *reinterpret_cast<const float2*>(fbase + ii * CFEAT);
        acc0 = fmaf(wi, f2.x, acc0);
        acc1 = fmaf(wi, f2.y, acc1);
    }
    float* oq = out + q * OUTC;
    oq[2 * lane]     = acc0;
    oq[2 * lane + 1] = acc1;

    // positional encoding: channels 64..114 = [xyz(3), sin(24), cos(24)]
    #pragma unroll
    for (int j0p = 0; j0p < 51; j0p += 32) {
        int j = j0p + lane;
        if (j < 51) {
            float vv;
            if (j < 3) {
                vv = (j == 0) ? qx : ((j == 1) ? qy : qz);
            } else {
                int s = (j < 27) ? (j - 3) : (j - 27);
                int d = s % 3;
                float coord = (d == 0) ? qx : ((d == 1) ? qy : qz);
                float a = coord * (float)(1 << (s / 3));
                vv = (j < 27) ? __sinf(a) : __cosf(a);
            }
            oq[64 + j] = vv;
        }
    }
}

extern "C" void kernel_launch(void* const* d_in, const int* in_sizes, int n_in,
                              void* d_out, int out_size) {
    const float* xyz  = (const float*)d_in[0];   // [1, P, 3]
    const float* pcd  = (const float*)d_in[1];   // [1, N, 3]
    const float* feat = (const float*)d_in[2];   // [1, N, 64]
    float* out = (float*)d_out;                  // [1, P, 115]
    const int P = in_sizes[0] / 3;
    const int N = in_sizes[1] / 3;

    const int nb = (N + BTHR - 1) / BTHR;        // 64 blocks: fully resident
    build_kernel<<<nb, BTHR>>>(pcd, N);
    knn_kernel<<<(P + WPB - 1) / WPB, WPB * 32>>>(xyz, feat, out, P);
}

// round 11
// speedup vs baseline: 1.6928x; 1.6928x over previous
#include <cuda_runtime.h>
#include <cstdint>

// Problem constants (fixed by the dataset: B=1, P=8192, N=16384, C=64)
#define GRID_DIM 10
#define NCELLS   (GRID_DIM * GRID_DIM * GRID_DIM)
#define NPTS_MAX 16384
#define CFEAT    64
#define OUTC     115          // 64 fcd + 3 xyz + 24 sin + 24 cos
#define KNN      10
#define R2F      0.01f
#define RADIUSF  0.1f
#define CANDMAX  128          // per-query candidate cap (E ~ 68.6, sigma ~ 8.3)
#define WPB      4            // warps (queries) per block
#define BTHR     256          // build threads per block
#define UINF     0xFFFFFFFFu

// ---- scratch: static __device__ arrays (no allocation allowed) ----
__device__ int    g_cntH[2][NCELLS];         // histogram, ping-pong by epoch parity
__device__ int    g_cntS[2][NCELLS];         // scatter offset counters, ping-pong
__device__ int    g_entry;                   // monotonic across replays
__device__ int    g_done;                    // monotonic across replays
__device__ int    g_cell_start[NCELLS + 1];
__device__ float4 g_sorted[NPTS_MAX + 96];   // {x,y,z,|p|^2}; +96 zero pad (safe OOS loads)
__device__ int    g_sidx[NPTS_MAX];          // original index

__device__ __forceinline__ int cell_coord(float v) {
    int c = (int)(v * 10.0f);
    return c < 0 ? 0 : (c > 9 ? 9 : c);
}
__device__ __forceinline__ int cell_of(float x, float y, float z) {
    return (cell_coord(z) * GRID_DIM + cell_coord(y)) * GRID_DIM + cell_coord(x);
}

// ---- build: count -> poll-all -> redundant parallel scan -> scatter ----
// 64 fully-resident blocks. One global sync (poll on monotonic g_done).
// Parity arrays: epoch E uses g_cnt*[E&1]; zeroes g_cnt*[1-(E&1)] for E+1.
__global__ void __launch_bounds__(BTHR)
build_kernel(const float* __restrict__ pcd, int N) {
    __shared__ int s_start[NCELLS];
    __shared__ int s_total;
    __shared__ int warp_sums[BTHR / 32];
    __shared__ int s_epoch;

    const int t   = threadIdx.x;
    const int bid = blockIdx.x;
    const int nb  = gridDim.x;
    const int i   = bid * BTHR + t;

    if (t == 0) s_epoch = atomicAdd(&g_entry, 1) / nb;
    __syncthreads();
    const int E = s_epoch;
    const int p = E & 1;

    // ---- count ----
    float x = 0.f, y = 0.f, z = 0.f, pp = 0.f;
    int c = 0;
    const bool valid = (i < N);
    if (valid) {
        x = pcd[3 * i]; y = pcd[3 * i + 1]; z = pcd[3 * i + 2];
        pp = __fadd_rn(__fadd_rn(__fmul_rn(x, x), __fmul_rn(y, y)),
                       __fmul_rn(z, z));            // |p|^2 as reference
        c = cell_of(x, y, z);
        atomicAdd(&g_cntH[p][c], 1);
    }
    __threadfence();
    __syncthreads();
    if (t == 0) {
        atomicAdd(&g_done, 1);
        while (*((volatile int*)&g_done) < (E + 1) * nb) __nanosleep(32);
    }
    __syncthreads();
    __threadfence();

    // ---- redundant parallel scan into smem (identical in every block) ----
    {
        const int lane = t & 31, wid = t >> 5;
        const int c0 = t * 4;
        int loc[4], pref = 0;
        #pragma unroll
        for (int r = 0; r < 4; r++) {
            int cc = c0 + r;
            int v = (cc < NCELLS) ? g_cntH[p][cc] : 0;
            loc[r] = pref; pref += v;
        }
        int inc = pref;
        #pragma unroll
        for (int off = 1; off < 32; off <<= 1) {
            int o = __shfl_up_sync(0xffffffffu, inc, off);
            if (lane >= off) inc += o;
        }
        if (lane == 31) warp_sums[wid] = inc;
        __syncthreads();
        if (wid == 0) {
            int v = (lane < BTHR / 32) ? warp_sums[lane] : 0;
            int s = v;
            #pragma unroll
            for (int off = 1; off < BTHR / 32; off <<= 1) {
                int o = __shfl_up_sync(0xffffffffu, s, off);
                if (lane >= off) s += o;
            }
            if (lane < BTHR / 32) warp_sums[lane] = s - v;
        }
        __syncthreads();
        const int base = warp_sums[wid] + (inc - pref);
        #pragma unroll
        for (int r = 0; r < 4; r++) {
            int cc = c0 + r;
            if (cc < NCELLS) s_start[cc] = base + loc[r];
        }
        if (t == BTHR - 1) s_total = base + pref;
    }
    __syncthreads();

    // ---- each block writes its 16-entry slice of g_cell_start[0..1000] ----
    if (t < 16) {
        int cc = bid * 16 + t;
        if (cc <= NCELLS)
            g_cell_start[cc] = (cc < NCELLS) ? s_start[cc] : s_total;
    }

    // ---- scatter ----
    if (valid) {
        int pos = s_start[c] + atomicAdd(&g_cntS[p][c], 1);
        g_sorted[pos] = make_float4(x, y, z, pp);
        g_sidx[pos] = i;
    }

    // ---- zero the other parity for the next epoch ----
    if (i < NCELLS) {
        g_cntH[1 - p][i] = 0;
        g_cntS[1 - p][i] = 0;
    }
}

// ---- main: warp-per-query radius KNN + aggregate + positional encoding ----
__global__ void __launch_bounds__(WPB * 32)
knn_kernel(const float* __restrict__ xyz,
           const float* __restrict__ feat,
           float* __restrict__ out, int P) {
    __shared__ uint2 buf[WPB][CANDMAX];    // {ordered_d2_bits, sorted_pos}

    const int w    = threadIdx.x >> 5;
    const int lane = threadIdx.x & 31;
    const int q    = blockIdx.x * WPB + w;
    if (q >= P) return;                    // warp-uniform

    const float qx = xyz[3 * q], qy = xyz[3 * q + 1], qz = xyz[3 * q + 2];
    const float qq = __fadd_rn(__fadd_rn(__fmul_rn(qx, qx), __fmul_rn(qy, qy)),
                               __fmul_rn(qz, qz));

    const int iy = cell_coord(qy), iz = cell_coord(qz);
    const int y0 = max(iy - 1, 0), y1 = min(iy + 1, GRID_DIM - 1);
    const int z0 = max(iz - 1, 0), z1 = min(iz + 1, GRID_DIM - 1);

    int count = 0;                          // warp-uniform candidate count
    for (int zz = z0; zz <= z1; zz++) {
        float dz = fmaxf(0.0f, fmaxf(0.1f * zz - qz, qz - 0.1f * (zz + 1)));
        float dz2 = dz * dz;
        for (int yy = y0; yy <= y1; yy++) {
            float dy = fmaxf(0.0f, fmaxf(0.1f * yy - qy, qy - 0.1f * (yy + 1)));
            float rowd2 = fmaf(dy, dy, dz2);
            if (rowd2 > R2F + 1e-6f) continue;
            float rx = sqrtf(fmaxf(R2F + 1e-7f - rowd2, 0.0f)) + 1e-6f;
            int xa = cell_coord(qx - rx);
            int xb = cell_coord(qx + rx);
            const int cbase = (zz * GRID_DIM + yy) * GRID_DIM;
            const int segS = g_cell_start[cbase + xa];
            const int segE = g_cell_start[cbase + xb + 1];
            // 64 points per iteration: 2 per lane, 2 independent LDG.128s
            for (int j0 = segS; j0 < segE; j0 += 64) {
                const int ja = j0 + lane;
                const int jb = ja + 32;
                float4 pa = g_sorted[ja];   // padded array: always safe
                float4 pb = g_sorted[jb];
                float dota = fmaf(qz, pa.z, fmaf(qy, pa.y, __fmul_rn(qx, pa.x)));
                float d2a  = __fsub_rn(__fadd_rn(qq, pa.w), __fmul_rn(2.0f, dota));
                float dotb = fmaf(qz, pb.z, fmaf(qy, pb.y, __fmul_rn(qx, pb.x)));
                float d2b  = __fsub_rn(__fadd_rn(qq, pb.w), __fmul_rn(2.0f, dotb));
                bool pra = (ja < segE) && (d2a < R2F);
                bool prb = (jb < segE) && (d2b < R2F);
                unsigned ba = __ballot_sync(0xffffffffu, pra);
                unsigned bb = __ballot_sync(0xffffffffu, prb);
                const unsigned mask = (1u << lane) - 1u;
                if (pra) {
                    int b = __float_as_int(d2a);
                    unsigned u = (unsigned)b ^ ((b >= 0) ? 0x80000000u : 0xFFFFFFFFu);
                    int pos = count + __popc(ba & mask);
                    if (pos < CANDMAX) buf[w][pos] = make_uint2(u, (unsigned)ja);
                }
                int ca = __popc(ba);
                if (prb) {
                    int b = __float_as_int(d2b);
                    unsigned u = (unsigned)b ^ ((b >= 0) ? 0x80000000u : 0xFFFFFFFFu);
                    int pos = count + ca + __popc(bb & mask);
                    if (pos < CANDMAX) buf[w][pos] = make_uint2(u, (unsigned)jb);
                }
                count += ca + __popc(bb);   // uniform across the warp
            }
        }
    }
    __syncwarp();

    const int m = min(count, CANDMAX);

    // per-lane slots in named registers (no arrays -> no dynamic indexing)
    unsigned vd0, vd1, vd2, vd3, vp0, vp1, vp2, vp3;
    {
        uint2 e0 = (lane      < m) ? buf[w][lane]      : make_uint2(UINF, 0u);
        uint2 e1 = (lane + 32 < m) ? buf[w][lane + 32] : make_uint2(UINF, 0u);
        uint2 e2 = (lane + 64 < m) ? buf[w][lane + 64] : make_uint2(UINF, 0u);
        uint2 e3 = (lane + 96 < m) ? buf[w][lane + 96] : make_uint2(UINF, 0u);
        vd0 = e0.x; vp0 = e0.y;  vd1 = e1.x; vp1 = e1.y;
        vd2 = e2.x; vp2 = e2.y;  vd3 = e3.x; vp3 = e3.y;
    }

    unsigned kd2 = UINF, kpos = 0u;
    #pragma unroll
    for (int i = 0; i < KNN; i++) {
        // static select-tree lane-min with (d2, pos, slot)
        bool c01 = (vd0 < vd1) || (vd0 == vd1 && vp0 <= vp1);
        unsigned m01 = c01 ? vd0 : vd1, p01 = c01 ? vp0 : vp1;
        int s01 = c01 ? 0 : 1;
        bool c23 = (vd2 < vd3) || (vd2 == vd3 && vp2 <= vp3);
        unsigned m23 = c23 ? vd2 : vd3, p23 = c23 ? vp2 : vp3;
        int s23 = c23 ? 2 : 3;
        bool cf = (m01 < m23) || (m01 == m23 && p01 <= p23);
        unsigned lmin = cf ? m01 : m23, lpos = cf ? p01 : p23;
        int lslot = cf ? s01 : s23;

        unsigned gmin = __reduce_min_sync(0xffffffffu, lmin);
        unsigned cnd  = (lmin == gmin) ? lpos : UINF;
        unsigned wpos = __reduce_min_sync(0xffffffffu, cnd);
        if (lane == i) { kd2 = gmin; kpos = wpos; }

        // clear exactly the winning slot (fully predicated, static)
        bool winner = (lmin == gmin) & (lpos == wpos);
        vd0 = (winner && lslot == 0) ? UINF : vd0;
        vd1 = (winner && lslot == 1) ? UINF : vd1;
        vd2 = (winner && lslot == 2) ? UINF : vd2;
        vd3 = (winner && lslot == 3) ? UINF : vd3;
    }

    // weights (per reference numerics)
    float wr = 0.0f;
    int nidx = 0;
    if (kd2 != UINF) {
        unsigned ub = kd2 ^ (((int)kd2 < 0) ? 0x80000000u : 0xFFFFFFFFu);
        float d2 = __int_as_float((int)ub);
        float dist = sqrtf(fmaxf(d2, 0.0f) + 1e-12f);
        if (dist < RADIUSF) wr = 1.0f / (dist + 1e-8f);
        nidx = g_sidx[kpos];                 // only winner lanes load this
    }
    float ws = wr;
    #pragma unroll
    for (int off = 16; off; off >>= 1) ws += __shfl_xor_sync(0xffffffffu, ws, off);
    float wn = wr / (ws + 1e-8f);

    // weighted feature gather: each lane owns channels (2*lane, 2*lane+1)
    const float* fbase = feat + 2 * lane;
    float acc0 = 0.0f, acc1 = 0.0f;
    #pragma unroll
    for (int i = 0; i < KNN; i++) {
        float wi = __shfl_sync(0xffffffffu, wn, i);
        int ii = __shfl_sync(0xffffffffu, nidx, i);
        const float2 f2 = *reinterpret_cast<const float2*>(fbase + ii * CFEAT);
        acc0 = fmaf(wi, f2.x, acc0);
        acc1 = fmaf(wi, f2.y, acc1);
    }
    float* oq = out + q * OUTC;
    oq[2 * lane]     = acc0;
    oq[2 * lane + 1] = acc1;

    // positional encoding: channels 64..114 = [xyz(3), sin(24), cos(24)]
    #pragma unroll
    for (int j0 = 0; j0 < 51; j0 += 32) {
        int j = j0 + lane;
        if (j < 51) {
            float vv;
            if (j < 3) {
                vv = (j == 0) ? qx : ((j == 1) ? qy : qz);
            } else {
                int s = (j < 27) ? (j - 3) : (j - 27);
                int d = s % 3;
                float coord = (d == 0) ? qx : ((d == 1) ? qy : qz);
                float a = coord * (float)(1 << (s / 3));
                vv = (j < 27) ? __sinf(a) : __cosf(a);
            }
            oq[64 + j] = vv;
        }
    }
}

extern "C" void kernel_launch(void* const* d_in, const int* in_sizes, int n_in,
                              void* d_out, int out_size) {
    const float* xyz  = (const float*)d_in[0];   // [1, P, 3]
    const float* pcd  = (const float*)d_in[1];   // [1, N, 3]
    const float* feat = (const float*)d_in[2];   // [1, N, 64]
    float* out = (float*)d_out;                  // [1, P, 115]
    const int P = in_sizes[0] / 3;
    const int N = in_sizes[1] / 3;

    const int nb = (N + BTHR - 1) / BTHR;        // 64 blocks: fully resident
    build_kernel<<<nb, BTHR>>>(pcd, N);
    knn_kernel<<<(P + WPB - 1) / WPB, WPB * 32>>>(xyz, feat, out, P);
}